// round 2
// baseline (speedup 1.0000x reference)
#include <cuda_runtime.h>
#include <cstdint>

// Problem constants
#define Tn   1024
#define Bn   64
#define Dn   32
#define Hn   512
#define KK   544          // H + D concatenated K dimension
#define NCTA 128
#define NTHR 256

// Scratch (device globals: allocation-free per harness rules)
__device__ float    g_xT[(size_t)Tn * Dn * Bn];            // [t][d][b]  8 MB
__device__ float    g_hist[(size_t)(Tn + 1) * Hn * Bn];    // [t][h][b]  ~134 MB
__device__ unsigned g_arrive;

// SMEM layout (floats): h[544*64] | w_dup[544*16*2] | gates[16*64] | c[256] | bias[16]
#define SMEM_FLOATS (KK*Bn + KK*32 + 16*Bn + NTHR + 16)
#define SMEM_BYTES  (SMEM_FLOATS * 4)

// ---------------------------------------------------------------------------
// Prep: transpose x (B,D,T)->(T,D,B), zero hist[0], reset barrier counter
// ---------------------------------------------------------------------------
__global__ void lstm_prep_kernel(const float* __restrict__ x) {
    long long idx = (long long)blockIdx.x * blockDim.x + threadIdx.x;
    if (idx == 0) g_arrive = 0u;
    if (idx < Hn * Bn) g_hist[idx] = 0.f;
    const long long total = (long long)Bn * Dn * Tn;
    if (idx < total) {
        int t = (int)(idx % Tn);
        int d = (int)((idx / Tn) % Dn);
        int b = (int)(idx / ((long long)Tn * Dn));
        g_xT[(size_t)t * Dn * Bn + d * Bn + b] = x[idx];
    }
}

// ---------------------------------------------------------------------------
// Persistent LSTM recurrence
// ---------------------------------------------------------------------------
extern __shared__ float smem[];

__global__ void __launch_bounds__(NTHR, 1) lstm_main_kernel(
    const float* __restrict__ W_ih,   // [4H, D]
    const float* __restrict__ W_hh,   // [4H, H]
    const float* __restrict__ b_ih,   // [4H]
    const float* __restrict__ b_hh)   // [4H]
{
    float* sm_h     = smem;                      // [544][64]
    float* sm_w     = sm_h + KK * Bn;            // [544][16] float2 (w,w)
    float* sm_gates = sm_w + KK * 32;            // [16][64]
    float* sm_c     = sm_gates + 16 * Bn;        // [4][64] -> indexed by tid
    float* sm_bias  = sm_c + NTHR;               // [16]

    const int tid = threadIdx.x;
    const int cta = blockIdx.x;

    // ---- one-time: load W slice (dup f32x2) + bias, zero c ----
    for (int i = tid; i < 16 * KK; i += NTHR) {
        int k = i >> 4, nn = i & 15;
        int gate = nn >> 2, hi = nn & 3;
        int row = gate * Hn + cta * 4 + hi;
        float w = (k < Hn) ? W_hh[(size_t)row * Hn + k]
                           : W_ih[(size_t)row * Dn + (k - Hn)];
        ((float2*)sm_w)[k * 16 + nn] = make_float2(w, w);
    }
    if (tid < 16) {
        int gate = tid >> 2, hi = tid & 3;
        int row = gate * Hn + cta * 4 + hi;
        sm_bias[tid] = b_ih[row] + b_hh[row];
    }
    sm_c[tid] = 0.f;
    __syncthreads();

    const int n  = tid & 15;   // gate-row within CTA: gate = n>>2, hi = n&3
    const int bq = tid >> 4;   // batch quad
    const int b0 = bq * 4;

    for (int t = 0; t < Tn; ++t) {
        // ---- stage h_{t} (k-major) + x_t into SMEM ----
        {
            const float4* srch = (const float4*)(g_hist + (size_t)t * Hn * Bn);
            const float4* srcx = (const float4*)(g_xT + (size_t)t * Dn * Bn);
            float4* dst = (float4*)sm_h;
            #pragma unroll
            for (int i = 0; i < (Hn * Bn / 4) / NTHR; ++i)      // 32 iters
                dst[tid + i * NTHR] = __ldcg(srch + tid + i * NTHR);
            #pragma unroll
            for (int i = 0; i < (Dn * Bn / 4) / NTHR; ++i)      // 2 iters
                dst[Hn * Bn / 4 + tid + i * NTHR] = __ldcg(srcx + tid + i * NTHR);
        }
        __syncthreads();

        // ---- GEMM: acc[n][b0..b0+3] = sum_k w[k][n] * hx[k][b] (f32x2) ----
        unsigned long long acc0 = 0ull, acc1 = 0ull;
        const unsigned long long* hp = (const unsigned long long*)sm_h + bq * 2;
        const unsigned long long* wp = (const unsigned long long*)sm_w + n;
        #pragma unroll 8
        for (int k = 0; k < KK; ++k) {
            unsigned long long w2 = wp[(size_t)k * 16];
            unsigned long long h0 = hp[(size_t)k * 32];
            unsigned long long h1 = hp[(size_t)k * 32 + 1];
            asm("fma.rn.f32x2 %0, %1, %2, %0;" : "+l"(acc0) : "l"(w2), "l"(h0));
            asm("fma.rn.f32x2 %0, %1, %2, %0;" : "+l"(acc1) : "l"(w2), "l"(h1));
        }

        // ---- exchange gates via SMEM ----
        {
            float2 p0 = *(float2*)&acc0;
            float2 p1 = *(float2*)&acc1;
            sm_gates[n * Bn + b0 + 0] = p0.x;
            sm_gates[n * Bn + b0 + 1] = p0.y;
            sm_gates[n * Bn + b0 + 2] = p1.x;
            sm_gates[n * Bn + b0 + 3] = p1.y;
        }
        __syncthreads();

        // ---- LSTM cell epilogue: thread = (hi, b) ----
        {
            int hi = tid >> 6, b = tid & 63;
            float xi = sm_gates[(0 + hi)  * Bn + b] + sm_bias[0 + hi];
            float xf = sm_gates[(4 + hi)  * Bn + b] + sm_bias[4 + hi];
            float xg = sm_gates[(8 + hi)  * Bn + b] + sm_bias[8 + hi];
            float xo = sm_gates[(12 + hi) * Bn + b] + sm_bias[12 + hi];
            float ii = 1.f / (1.f + __expf(-xi));
            float ff = 1.f / (1.f + __expf(-xf));
            float gg = 1.f - 2.f / (__expf(2.f * xg) + 1.f);   // tanh
            float oo = 1.f / (1.f + __expf(-xo));
            float c  = ff * sm_c[tid] + ii * gg;
            sm_c[tid] = c;
            float h  = oo * (1.f - 2.f / (__expf(2.f * c) + 1.f));
            g_hist[(size_t)(t + 1) * Hn * Bn + (cta * 4 + hi) * Bn + b] = h;
        }
        __threadfence();
        __syncthreads();

        // ---- global step barrier (monotonic counter) ----
        if (tid == 0) {
            atomicAdd(&g_arrive, 1u);
            unsigned target = (unsigned)(t + 1) * NCTA;
            unsigned v;
            for (;;) {
                asm volatile("ld.acquire.gpu.u32 %0, [%1];"
                             : "=r"(v) : "l"(&g_arrive) : "memory");
                if (v >= target) break;
                __nanosleep(64);
            }
        }
        __syncthreads();
    }
}

// ---------------------------------------------------------------------------
// Conv1d(H,1,kernel=1): pred[b][t] = sum_h h[t+1][h][b]*cw[h] + cb
// ---------------------------------------------------------------------------
__global__ void lstm_conv_kernel(const float* __restrict__ cw,
                                 const float* __restrict__ cb,
                                 float* __restrict__ out)
{
    int t = blockIdx.x;
    int b = threadIdx.x;
    const float* hp = g_hist + (size_t)(t + 1) * Hn * Bn + b;
    float acc = 0.f;
    #pragma unroll 8
    for (int h = 0; h < Hn; ++h)
        acc += __ldcg(hp + (size_t)h * Bn) * __ldg(cw + h);
    out[(size_t)b * Tn + t] = acc + cb[0];
}

// ---------------------------------------------------------------------------
extern "C" void kernel_launch(void* const* d_in, const int* in_sizes, int n_in,
                              void* d_out, int out_size)
{
    const float* x    = (const float*)d_in[0];  // (B, D, T)
    const float* W_ih = (const float*)d_in[1];  // (4H, D)
    const float* W_hh = (const float*)d_in[2];  // (4H, H)
    const float* b_ih = (const float*)d_in[3];  // (4H,)
    const float* b_hh = (const float*)d_in[4];  // (4H,)
    const float* cw   = (const float*)d_in[5];  // (1, H, 1)
    const float* cb   = (const float*)d_in[6];  // (1,)
    float* out = (float*)d_out;                 // (B, 1, T)

    cudaFuncSetAttribute(lstm_main_kernel,
                         cudaFuncAttributeMaxDynamicSharedMemorySize, SMEM_BYTES);

    lstm_prep_kernel<<<(Bn * Dn * Tn + 255) / 256, 256>>>(x);
    lstm_main_kernel<<<NCTA, NTHR, SMEM_BYTES>>>(W_ih, W_hh, b_ih, b_hh);
    lstm_conv_kernel<<<Tn, Bn>>>(cw, cb, out);
}